// round 12
// baseline (speedup 1.0000x reference)
#include <cuda_runtime.h>
#include <cuda_fp16.h>
#include <cstdint>

// CNF_plain via HMMA fp16 (mma.sync m16n8k16 f16, fp32 accum):
//   bacc = h @ W2,  racc = s1 @ E,  E = W2 .* (W1[:8,:]^T W3^T)
// A: h single fp16 plane; s1 fragments derived in regs (HFMA2 1-h*h).
// B: W2^T, E^T split fp16 hi+lo (4 MMA passes total).
// R12: warp tiles m64 x n16 (2m x 8n) minimize A/B reuse traffic:
// 512KB smem reads/tile vs 768KB. 512 threads, TILE_M=128.

#define Hh 128
#define Dd 8
#define THREADS 512
#define NBLK 148
#define TILE_M 128

#define ASTR 68   // u32 per A row (136 fp16 = 272B)
#define BSTR 68

// SMEM byte offsets
#define SM_HF   0          // 34816
#define SM_WH   34816
#define SM_WL   69632
#define SM_EH   104448
#define SM_EL   139264
#define SM_W1   174080     // 4608
#define SM_W3   178688     // 4096
#define SM_B1   182784
#define SM_B2   183296
#define SM_B3   183808
#define SM_PART 183872     // 8*128*9*4 = 36864
#define SM_TOTAL 220736

static __device__ unsigned short g_wh[16384];  // [j][i] = f16_hi(W2[i,j])
static __device__ unsigned short g_wl[16384];
static __device__ unsigned short g_eh[16384];  // [j][i] = f16_hi(E[i,j])
static __device__ unsigned short g_el[16384];

__global__ void prep(const float* __restrict__ W1, const float* __restrict__ W2,
                     const float* __restrict__ W3) {
    int idx = blockIdx.x * blockDim.x + threadIdx.x;
    if (idx >= 16384) return;
    int j = idx >> 7, i = idx & 127;
    float c = 0.f;
#pragma unroll
    for (int d = 0; d < Dd; d++) c = fmaf(W1[d * Hh + i], W3[j * Dd + d], c);
    float w2 = W2[i * Hh + j];
    float e  = w2 * c;
    __half h;
    h = __float2half_rn(w2);
    g_wh[idx] = __half_as_ushort(h);
    g_wl[idx] = __half_as_ushort(__float2half_rn(w2 - __half2float(h)));
    h = __float2half_rn(e);
    g_eh[idx] = __half_as_ushort(h);
    g_el[idx] = __half_as_ushort(__float2half_rn(e - __half2float(h)));
}

__device__ __forceinline__ float tanha(float x) {
    float y; asm("tanh.approx.f32 %0,%1;" : "=f"(y) : "f"(x)); return y;
}

__device__ __forceinline__ uint32_t pkh2(float a, float b) {
    __half2 h = __floats2half2_rn(a, b);
    return *reinterpret_cast<uint32_t*>(&h);
}

__device__ __forceinline__ uint32_t s_from_h(uint32_t h) {
    __half2 hh = *reinterpret_cast<__half2*>(&h);
    __half2 s = __hfma2(__hneg2(hh), hh, __float2half2_rn(1.0f));
    return *reinterpret_cast<uint32_t*>(&s);
}

__device__ __forceinline__ void mmaf16(float* c, const uint32_t* a,
                                       const uint32_t* b) {
    asm volatile(
        "mma.sync.aligned.m16n8k16.row.col.f32.f16.f16.f32 "
        "{%0,%1,%2,%3}, {%4,%5,%6,%7}, {%8,%9}, {%0,%1,%2,%3};"
        : "+f"(c[0]), "+f"(c[1]), "+f"(c[2]), "+f"(c[3])
        : "r"(a[0]), "r"(a[1]), "r"(a[2]), "r"(a[3]), "r"(b[0]), "r"(b[1]));
}

__device__ __forceinline__ void ldsm4(uint32_t* r, uint32_t a) {
    asm volatile("ldmatrix.sync.aligned.m8n8.x4.shared.b16 {%0,%1,%2,%3},[%4];"
                 : "=r"(r[0]), "=r"(r[1]), "=r"(r[2]), "=r"(r[3]) : "r"(a));
}

__device__ __forceinline__ uint32_t s2u(const void* p) {
    uint32_t a;
    asm("{.reg .u64 t; cvta.to.shared.u64 t, %1; cvt.u32.u64 %0, t;}"
        : "=r"(a) : "l"(p));
    return a;
}

__global__ __launch_bounds__(THREADS, 1)
void cnf_mma(const float* __restrict__ z, const float* __restrict__ tptr,
             const float* __restrict__ W1, const float* __restrict__ b1,
             const float* __restrict__ b2,
             const float* __restrict__ W3, const float* __restrict__ b3,
             float* __restrict__ out, int B) {
    extern __shared__ char smem[];
    uint32_t* Hf = (uint32_t*)(smem + SM_HF);
    float* W1s = (float*)(smem + SM_W1);
    float* W3s = (float*)(smem + SM_W3);
    float* b1s = (float*)(smem + SM_B1);
    float* b2s = (float*)(smem + SM_B2);
    float* b3s = (float*)(smem + SM_B3);
    float* part = (float*)(smem + SM_PART);   // [8 wn][128 m][9]

    const int tid = threadIdx.x;
    const int wid = tid >> 5, lane = tid & 31;
    const int wm = wid >> 3;          // m-half (64 rows)
    const int wn = wid & 7;           // n-eighth (16 cols)
    const int lq = lane & 3, lr = lane >> 2;

    // ---- stage B planes (pad 256B -> 272B rows) ----
    {
        const uint4* s0 = (const uint4*)g_wh;
        const uint4* s1 = (const uint4*)g_wl;
        const uint4* s2 = (const uint4*)g_eh;
        const uint4* s3 = (const uint4*)g_el;
        uint4* d0 = (uint4*)(smem + SM_WH);
        uint4* d1 = (uint4*)(smem + SM_WL);
        uint4* d2 = (uint4*)(smem + SM_EH);
        uint4* d3 = (uint4*)(smem + SM_EL);
        for (int k = tid; k < 2048; k += THREADS) {
            int j = k >> 4, c = k & 15;
            int dsti = j * 17 + c;
            d0[dsti] = s0[k]; d1[dsti] = s1[k];
            d2[dsti] = s2[k]; d3[dsti] = s3[k];
        }
    }
    for (int k = tid; k < 9 * Hh; k += THREADS) W1s[k] = W1[k];
    for (int k = tid; k < Hh * Dd; k += THREADS) W3s[k] = W3[k];
    if (tid < Hh) { b1s[tid] = b1[tid]; b2s[tid] = b2[tid]; }
    if (tid < Dd) b3s[tid] = b3[tid];
    __syncthreads();

    const float t = tptr[0];
    const int m = tid >> 2;           // phase-A sample (0..127)
    const int iq = tid & 3;           // phase-A i-quarter

    // ---- ldmatrix per-thread addresses ----
    const int grp = lane >> 3, l7 = lane & 7;
    // A frags: grp0:(m+0,k+0) grp1:(m+8,k+0) grp2:(m+0,k+8) grp3:(m+8,k+8)
    uint32_t sAh[4];
#pragma unroll
    for (int mt = 0; mt < 4; mt++) {
        uint32_t off = (uint32_t)(((wm * 64 + mt * 16 + l7 + (grp & 1) * 8) * ASTR
                                   + (grp >> 1) * 4) * 4);
        sAh[mt] = s2u(smem + SM_HF) + off;
    }
    // B frag: grp0:(n+0,k+0) grp1:(n+0,k+8) grp2:(n+8,k+0) grp3:(n+8,k+8)
    uint32_t sWh, sWl, sEh, sEl;
    {
        uint32_t off = (uint32_t)(((wn * 16 + l7 + (grp >> 1) * 8) * BSTR
                                   + (grp & 1) * 4) * 4);
        sWh = s2u(smem + SM_WH) + off;
        sWl = s2u(smem + SM_WL) + off;
        sEh = s2u(smem + SM_EH) + off;
        sEl = s2u(smem + SM_EL) + off;
    }

    const int nTiles = B / TILE_M;
    for (int tile = blockIdx.x; tile < nTiles; tile += gridDim.x) {
        // ================= phase A: layer 1, fp16 h plane =================
        {
            const int mg = tile * TILE_M + m;
            float4 z0 = *(const float4*)(z + (size_t)mg * 8);
            float4 z1 = *(const float4*)(z + (size_t)mg * 8 + 4);
            float zv[8] = {z0.x, z0.y, z0.z, z0.w, z1.x, z1.y, z1.z, z1.w};
#pragma unroll
            for (int c8 = 0; c8 < 8; c8++) {
                int i0 = iq * 32 + c8 * 4;
                float4 acc = *(const float4*)(b1s + i0);
                float4 wt = *(const float4*)(W1s + 8 * Hh + i0);
                acc.x = fmaf(t, wt.x, acc.x); acc.y = fmaf(t, wt.y, acc.y);
                acc.z = fmaf(t, wt.z, acc.z); acc.w = fmaf(t, wt.w, acc.w);
#pragma unroll
                for (int d = 0; d < 8; d++) {
                    float4 w = *(const float4*)(W1s + d * Hh + i0);
                    acc.x = fmaf(zv[d], w.x, acc.x);
                    acc.y = fmaf(zv[d], w.y, acc.y);
                    acc.z = fmaf(zv[d], w.z, acc.z);
                    acc.w = fmaf(zv[d], w.w, acc.w);
                }
                int o = m * ASTR + iq * 16 + c8 * 2;
                *(uint2*)&Hf[o] = make_uint2(pkh2(tanha(acc.x), tanha(acc.y)),
                                             pkh2(tanha(acc.z), tanha(acc.w)));
            }
        }
        __syncthreads();

        // ================= phase B: HMMA fp16 =================
        float cb[4][2][4], cr[4][2][4];
#pragma unroll
        for (int mt = 0; mt < 4; mt++)
#pragma unroll
            for (int nt = 0; nt < 2; nt++)
#pragma unroll
                for (int q = 0; q < 4; q++) { cb[mt][nt][q] = 0.f; cr[mt][nt][q] = 0.f; }

#pragma unroll 1
        for (int kt = 0; kt < 8; kt++) {
            const uint32_t ka = (uint32_t)(kt * 32);
            uint32_t bw[4], bl[4], be[4], bel[4];
            ldsm4(bw, sWh + ka);
            ldsm4(bl, sWl + ka);
            ldsm4(be, sEh + ka);
            ldsm4(bel, sEl + ka);
#pragma unroll
            for (int mt = 0; mt < 4; mt++) {
                uint32_t ah[4], as_[4];
                ldsm4(ah, sAh[mt] + ka);
#pragma unroll
                for (int r = 0; r < 4; r++) as_[r] = s_from_h(ah[r]);
#pragma unroll
                for (int nt = 0; nt < 2; nt++) {
                    mmaf16(cb[mt][nt], ah, bw + nt * 2);
                    mmaf16(cb[mt][nt], ah, bl + nt * 2);
                    mmaf16(cr[mt][nt], as_, be + nt * 2);
                    mmaf16(cr[mt][nt], as_, bel + nt * 2);
                }
            }
        }
        __syncthreads();

        // ================= epilogue =================
#pragma unroll
        for (int mt = 0; mt < 4; mt++)
#pragma unroll
            for (int rh = 0; rh < 2; rh++) {
                float od[8] = {0.f, 0.f, 0.f, 0.f, 0.f, 0.f, 0.f, 0.f};
                float tr = 0.f;
#pragma unroll
                for (int nt = 0; nt < 2; nt++)
#pragma unroll
                    for (int q = 0; q < 2; q++) {
                        int j = wn * 16 + nt * 8 + lq * 2 + q;
                        float bv = cb[mt][nt][rh * 2 + q] + b2s[j];
                        float h2 = tanha(bv);
                        float s2v = fmaf(-h2, h2, 1.0f);
                        tr = fmaf(s2v, cr[mt][nt][rh * 2 + q], tr);
                        float4 lo = *(const float4*)&W3s[j * 8];
                        float4 hi = *(const float4*)&W3s[j * 8 + 4];
                        od[0] = fmaf(h2, lo.x, od[0]);
                        od[1] = fmaf(h2, lo.y, od[1]);
                        od[2] = fmaf(h2, lo.z, od[2]);
                        od[3] = fmaf(h2, lo.w, od[3]);
                        od[4] = fmaf(h2, hi.x, od[4]);
                        od[5] = fmaf(h2, hi.y, od[5]);
                        od[6] = fmaf(h2, hi.z, od[6]);
                        od[7] = fmaf(h2, hi.w, od[7]);
                    }
#pragma unroll
                for (int off = 1; off <= 2; off <<= 1) {
#pragma unroll
                    for (int k = 0; k < 8; k++)
                        od[k] += __shfl_xor_sync(0xffffffffu, od[k], off);
                    tr += __shfl_xor_sync(0xffffffffu, tr, off);
                }
                if (lq == 0) {
                    int ml = wm * 64 + mt * 16 + rh * 8 + lr;
                    float* pp = part + (wn * TILE_M + ml) * 9;
#pragma unroll
                    for (int k = 0; k < 8; k++) pp[k] = od[k];
                    pp[8] = tr;
                }
            }
        __syncthreads();

        // combine 8 n-eighths per sample
        if (tid < TILE_M) {
            float acc[9] = {0.f,0.f,0.f,0.f,0.f,0.f,0.f,0.f,0.f};
#pragma unroll
            for (int s = 0; s < 8; s++) {
                const float* pp = part + (s * TILE_M + tid) * 9;
#pragma unroll
                for (int k = 0; k < 9; k++) acc[k] += pp[k];
            }
            int mg = tile * TILE_M + tid;
            float* o = out + (size_t)mg * 8;
            float4 v0 = make_float4(acc[0] + b3s[0], acc[1] + b3s[1],
                                    acc[2] + b3s[2], acc[3] + b3s[3]);
            float4 v1 = make_float4(acc[4] + b3s[4], acc[5] + b3s[5],
                                    acc[6] + b3s[6], acc[7] + b3s[7]);
            *(float4*)o = v0;
            *(float4*)(o + 4) = v1;
            out[(size_t)B * 8 + mg] = -acc[8];
        }
        __syncthreads();
    }
}

extern "C" void kernel_launch(void* const* d_in, const int* in_sizes, int n_in,
                              void* d_out, int out_size) {
    const float* z  = (const float*)d_in[0];
    // d_in[1] = logp_z (unused by reference output)
    const float* t  = (const float*)d_in[2];
    const float* W1 = (const float*)d_in[3];
    const float* b1 = (const float*)d_in[4];
    const float* W2 = (const float*)d_in[5];
    const float* b2 = (const float*)d_in[6];
    const float* W3 = (const float*)d_in[7];
    const float* b3 = (const float*)d_in[8];
    float* out = (float*)d_out;
    int B = in_sizes[0] / Dd;

    cudaFuncSetAttribute(cnf_mma, cudaFuncAttributeMaxDynamicSharedMemorySize,
                         SM_TOTAL);

    prep<<<64, 256>>>(W1, W2, W3);
    cnf_mma<<<NBLK, THREADS, SM_TOTAL>>>(z, t, W1, b1, b2, W3, b3, out, B);
}

// round 13
// speedup vs baseline: 1.0716x; 1.0716x over previous
#include <cuda_runtime.h>
#include <cuda_fp16.h>
#include <cstdint>

// CNF_plain via HMMA fp16:
//   bacc = h @ W2,  racc = s1 @ E,  E = W2 .* (W1[:8,:]^T W3^T)
//   dz   = tanh(bacc+b2) @ W3  (ALSO via HMMA: acc-frag == A-frag layout)
// A: h single fp16 plane, s1 derived in regs; B: W2^T/E^T split hi+lo.
// R13: double-buffered Hf, 3 syncs/tile, MMA epilogue, spread-out MMA order.

#define Hh 128
#define Dd 8
#define THREADS 512
#define NBLK 148
#define TILE_M 128

#define ASTR 68   // u32 per A row (136 fp16 = 272B)
#define BSTR 68
#define HFU32 8704          // u32 per Hf buffer (128*68)

// SMEM byte offsets
#define SM_HF   0           // 2 x 34816
#define SM_WH   69632
#define SM_WL   104448
#define SM_EH   139264
#define SM_EL   174080
#define SM_W1   208896
#define SM_W3   213504
#define SM_B1   217600
#define SM_B2   218112
#define SM_B3   218624
#define SM_PTR  218688      // trace partials 8*128*4
#define SM_TOTAL 222784

static __device__ unsigned short g_wh[16384];  // [j][i] = f16_hi(W2[i,j])
static __device__ unsigned short g_wl[16384];
static __device__ unsigned short g_eh[16384];  // [j][i] = f16_hi(E[i,j])
static __device__ unsigned short g_el[16384];

__global__ void prep(const float* __restrict__ W1, const float* __restrict__ W2,
                     const float* __restrict__ W3) {
    int idx = blockIdx.x * blockDim.x + threadIdx.x;
    if (idx >= 16384) return;
    int j = idx >> 7, i = idx & 127;
    float c = 0.f;
#pragma unroll
    for (int d = 0; d < Dd; d++) c = fmaf(W1[d * Hh + i], W3[j * Dd + d], c);
    float w2 = W2[i * Hh + j];
    float e  = w2 * c;
    __half h;
    h = __float2half_rn(w2);
    g_wh[idx] = __half_as_ushort(h);
    g_wl[idx] = __half_as_ushort(__float2half_rn(w2 - __half2float(h)));
    h = __float2half_rn(e);
    g_eh[idx] = __half_as_ushort(h);
    g_el[idx] = __half_as_ushort(__float2half_rn(e - __half2float(h)));
}

__device__ __forceinline__ float tanha(float x) {
    float y; asm("tanh.approx.f32 %0,%1;" : "=f"(y) : "f"(x)); return y;
}

__device__ __forceinline__ uint32_t pkh2(float a, float b) {
    __half2 h = __floats2half2_rn(a, b);
    return *reinterpret_cast<uint32_t*>(&h);
}

__device__ __forceinline__ uint32_t s_from_h(uint32_t h) {
    __half2 hh = *reinterpret_cast<__half2*>(&h);
    __half2 s = __hfma2(__hneg2(hh), hh, __float2half2_rn(1.0f));
    return *reinterpret_cast<uint32_t*>(&s);
}

__device__ __forceinline__ void mmaf16(float* c, const uint32_t* a,
                                       const uint32_t* b) {
    asm volatile(
        "mma.sync.aligned.m16n8k16.row.col.f32.f16.f16.f32 "
        "{%0,%1,%2,%3}, {%4,%5,%6,%7}, {%8,%9}, {%0,%1,%2,%3};"
        : "+f"(c[0]), "+f"(c[1]), "+f"(c[2]), "+f"(c[3])
        : "r"(a[0]), "r"(a[1]), "r"(a[2]), "r"(a[3]), "r"(b[0]), "r"(b[1]));
}

__device__ __forceinline__ void ldsm4(uint32_t* r, uint32_t a) {
    asm volatile("ldmatrix.sync.aligned.m8n8.x4.shared.b16 {%0,%1,%2,%3},[%4];"
                 : "=r"(r[0]), "=r"(r[1]), "=r"(r[2]), "=r"(r[3]) : "r"(a));
}

__device__ __forceinline__ uint32_t s2u(const void* p) {
    uint32_t a;
    asm("{.reg .u64 t; cvta.to.shared.u64 t, %1; cvt.u32.u64 %0, t;}"
        : "=r"(a) : "l"(p));
    return a;
}

__global__ __launch_bounds__(THREADS, 1)
void cnf_mma(const float* __restrict__ z, const float* __restrict__ tptr,
             const float* __restrict__ W1, const float* __restrict__ b1,
             const float* __restrict__ b2,
             const float* __restrict__ W3, const float* __restrict__ b3,
             float* __restrict__ out, int B) {
    extern __shared__ char smem[];
    uint32_t* Hf = (uint32_t*)(smem + SM_HF);
    float* W1s = (float*)(smem + SM_W1);
    float* W3s = (float*)(smem + SM_W3);
    float* b1s = (float*)(smem + SM_B1);
    float* b2s = (float*)(smem + SM_B2);
    float* b3s = (float*)(smem + SM_B3);
    float* ptr_ = (float*)(smem + SM_PTR);    // [8 wn][128] trace partials

    const int tid = threadIdx.x;
    const int wid = tid >> 5, lane = tid & 31;
    const int wm = wid >> 3;          // m-half (64 rows)
    const int wn = wid & 7;           // n-eighth (16 cols)
    const int lq = lane & 3, lr = lane >> 2;

    // ---- stage B planes ----
    {
        const uint4* s0 = (const uint4*)g_wh;
        const uint4* s1 = (const uint4*)g_wl;
        const uint4* s2 = (const uint4*)g_eh;
        const uint4* s3 = (const uint4*)g_el;
        uint4* d0 = (uint4*)(smem + SM_WH);
        uint4* d1 = (uint4*)(smem + SM_WL);
        uint4* d2 = (uint4*)(smem + SM_EH);
        uint4* d3 = (uint4*)(smem + SM_EL);
        for (int k = tid; k < 2048; k += THREADS) {
            int j = k >> 4, c = k & 15;
            int dsti = j * 17 + c;
            d0[dsti] = s0[k]; d1[dsti] = s1[k];
            d2[dsti] = s2[k]; d3[dsti] = s3[k];
        }
    }
    for (int k = tid; k < 9 * Hh; k += THREADS) W1s[k] = W1[k];
    for (int k = tid; k < Hh * Dd; k += THREADS) W3s[k] = W3[k];
    if (tid < Hh) { b1s[tid] = b1[tid]; b2s[tid] = b2[tid]; }
    if (tid < Dd) b3s[tid] = b3[tid];
    __syncthreads();

    const float t = tptr[0];
    const int m = tid >> 2;           // phase-A sample (0..127)
    const int iq = tid & 3;           // phase-A i-quarter

    // ---- ldmatrix per-thread addresses (buffer 0 base) ----
    const int grp = lane >> 3, l7 = lane & 7;
    uint32_t sAh[4];
#pragma unroll
    for (int mt = 0; mt < 4; mt++) {
        uint32_t off = (uint32_t)(((wm * 64 + mt * 16 + l7 + (grp & 1) * 8) * ASTR
                                   + (grp >> 1) * 4) * 4);
        sAh[mt] = s2u(smem + SM_HF) + off;
    }
    uint32_t sWh, sWl, sEh, sEl;
    {
        uint32_t off = (uint32_t)(((wn * 16 + l7 + (grp >> 1) * 8) * BSTR
                                   + (grp & 1) * 4) * 4);
        sWh = s2u(smem + SM_WH) + off;
        sWl = s2u(smem + SM_WL) + off;
        sEh = s2u(smem + SM_EH) + off;
        sEl = s2u(smem + SM_EL) + off;
    }

    // W3 b-frag (warp-constant): b0 = W3[j0+lq*2..+1][d=lr], b1 = +8
    const float bA = b2s[wn * 16 + lq * 2];
    const float bB = b2s[wn * 16 + lq * 2 + 1];
    const float bC = b2s[wn * 16 + 8 + lq * 2];
    const float bD = b2s[wn * 16 + 9 + lq * 2];
    uint32_t w3b[2];
    {
        int j0 = wn * 16 + lq * 2;
        w3b[0] = pkh2(W3s[j0 * 8 + lr], W3s[(j0 + 1) * 8 + lr]);
        w3b[1] = pkh2(W3s[(j0 + 8) * 8 + lr], W3s[(j0 + 9) * 8 + lr]);
    }

    const int nTiles = B / TILE_M;

    // ---- phase A lambda-ish macro (writes buffer bsel) ----
#define PHASE_A(TILEV, BSEL) do {                                             \
        const int mg = (TILEV) * TILE_M + m;                                  \
        float4 z0 = *(const float4*)(z + (size_t)mg * 8);                     \
        float4 z1 = *(const float4*)(z + (size_t)mg * 8 + 4);                 \
        float zv[8] = {z0.x, z0.y, z0.z, z0.w, z1.x, z1.y, z1.z, z1.w};       \
        uint32_t* HfW = Hf + (BSEL) * HFU32;                                  \
        _Pragma("unroll")                                                     \
        for (int c8 = 0; c8 < 8; c8++) {                                      \
            int i0 = iq * 32 + c8 * 4;                                        \
            float4 acc = *(const float4*)(b1s + i0);                          \
            float4 wt = *(const float4*)(W1s + 8 * Hh + i0);                  \
            acc.x = fmaf(t, wt.x, acc.x); acc.y = fmaf(t, wt.y, acc.y);       \
            acc.z = fmaf(t, wt.z, acc.z); acc.w = fmaf(t, wt.w, acc.w);       \
            _Pragma("unroll")                                                 \
            for (int d = 0; d < 8; d++) {                                     \
                float4 w = *(const float4*)(W1s + d * Hh + i0);               \
                acc.x = fmaf(zv[d], w.x, acc.x);                              \
                acc.y = fmaf(zv[d], w.y, acc.y);                              \
                acc.z = fmaf(zv[d], w.z, acc.z);                              \
                acc.w = fmaf(zv[d], w.w, acc.w);                              \
            }                                                                 \
            int o = m * ASTR + iq * 16 + c8 * 2;                              \
            *(uint2*)&HfW[o] = make_uint2(pkh2(tanha(acc.x), tanha(acc.y)),   \
                                          pkh2(tanha(acc.z), tanha(acc.w))); \
        }                                                                     \
    } while (0)

    int tile = blockIdx.x;
    if (tile < nTiles) PHASE_A(tile, 0);
    __syncthreads();

    int buf = 0;
    for (; tile < nTiles; tile += gridDim.x) {
        const uint32_t bofs = (uint32_t)(buf * 34816);

        // ================= MMA phase (reads Hf[buf]) =================
        float cb[4][2][4], cr[4][2][4];
#pragma unroll
        for (int mt = 0; mt < 4; mt++)
#pragma unroll
            for (int nt = 0; nt < 2; nt++)
#pragma unroll
                for (int q = 0; q < 4; q++) { cb[mt][nt][q] = 0.f; cr[mt][nt][q] = 0.f; }

#pragma unroll 1
        for (int kt = 0; kt < 8; kt++) {
            const uint32_t ka = (uint32_t)(kt * 32);
            uint32_t bw[4], bl[4], be[4], bel[4];
            ldsm4(bw, sWh + ka);
            ldsm4(bl, sWl + ka);
            ldsm4(be, sEh + ka);
            ldsm4(bel, sEl + ka);
#pragma unroll
            for (int mt = 0; mt < 4; mt++) {
                uint32_t ah[4], as_[4];
                ldsm4(ah, sAh[mt] + bofs + ka);
#pragma unroll
                for (int r = 0; r < 4; r++) as_[r] = s_from_h(ah[r]);
                // spread same-accumulator MMAs 4 apart
                mmaf16(cb[mt][0], ah, bw);
                mmaf16(cb[mt][1], ah, bw + 2);
                mmaf16(cr[mt][0], as_, be);
                mmaf16(cr[mt][1], as_, be + 2);
                mmaf16(cb[mt][0], ah, bl);
                mmaf16(cb[mt][1], ah, bl + 2);
                mmaf16(cr[mt][0], as_, bel);
                mmaf16(cr[mt][1], as_, bel + 2);
            }
        }
        __syncthreads();   // all MMA reads of Hf[buf] complete

        // ========== epilogue: dz via HMMA, trace scalar ==========
        // dz partials alias the just-consumed Hf buffer
        float* pdz = (float*)(smem + SM_HF + buf * 34816);  // [8 wn][128][8]
#pragma unroll
        for (int mt = 0; mt < 4; mt++) {
            float h00 = tanha(cb[mt][0][0] + bA), h01 = tanha(cb[mt][0][1] + bB);
            float h10 = tanha(cb[mt][1][0] + bC), h11 = tanha(cb[mt][1][1] + bD);
            float g00 = tanha(cb[mt][0][2] + bA), g01 = tanha(cb[mt][0][3] + bB);
            float g10 = tanha(cb[mt][1][2] + bC), g11 = tanha(cb[mt][1][3] + bD);
            uint32_t a[4] = {pkh2(h00, h01), pkh2(g00, g01),
                             pkh2(h10, h11), pkh2(g10, g11)};
            float dc[4] = {0.f, 0.f, 0.f, 0.f};
            mmaf16(dc, a, w3b);
            float trl = fmaf(fmaf(-h00, h00, 1.f), cr[mt][0][0], 0.f);
            trl = fmaf(fmaf(-h01, h01, 1.f), cr[mt][0][1], trl);
            trl = fmaf(fmaf(-h10, h10, 1.f), cr[mt][1][0], trl);
            trl = fmaf(fmaf(-h11, h11, 1.f), cr[mt][1][1], trl);
            float trh = fmaf(fmaf(-g00, g00, 1.f), cr[mt][0][2], 0.f);
            trh = fmaf(fmaf(-g01, g01, 1.f), cr[mt][0][3], trh);
            trh = fmaf(fmaf(-g10, g10, 1.f), cr[mt][1][2], trh);
            trh = fmaf(fmaf(-g11, g11, 1.f), cr[mt][1][3], trh);
            trl += __shfl_xor_sync(0xffffffffu, trl, 1);
            trl += __shfl_xor_sync(0xffffffffu, trl, 2);
            trh += __shfl_xor_sync(0xffffffffu, trh, 1);
            trh += __shfl_xor_sync(0xffffffffu, trh, 2);
            int row0 = wm * 64 + mt * 16 + lr;
            *(float2*)&pdz[(wn * 128 + row0) * 8 + lq * 2] =
                make_float2(dc[0], dc[1]);
            *(float2*)&pdz[(wn * 128 + row0 + 8) * 8 + lq * 2] =
                make_float2(dc[2], dc[3]);
            if (lq == 0) {
                ptr_[wn * 128 + row0] = trl;
                ptr_[wn * 128 + row0 + 8] = trh;
            }
        }

        // ========== phase A for next tile -> other buffer ==========
        {
            int tnext = tile + gridDim.x;
            if (tnext < nTiles) PHASE_A(tnext, buf ^ 1);
        }
        __syncthreads();

        // ========== combine 8 n-eighths per sample ==========
        if (tid < TILE_M) {
            float a0 = 0.f, a1 = 0.f, a2 = 0.f, a3 = 0.f;
            float a4 = 0.f, a5 = 0.f, a6 = 0.f, a7 = 0.f, trs = 0.f;
#pragma unroll
            for (int s = 0; s < 8; s++) {
                const float* pp = pdz + (s * 128 + tid) * 8;
                float4 x = *(const float4*)pp;
                float4 y = *(const float4*)(pp + 4);
                a0 += x.x; a1 += x.y; a2 += x.z; a3 += x.w;
                a4 += y.x; a5 += y.y; a6 += y.z; a7 += y.w;
                trs += ptr_[s * 128 + tid];
            }
            int mg = tile * TILE_M + tid;
            float* o = out + (size_t)mg * 8;
            *(float4*)o = make_float4(a0 + b3s[0], a1 + b3s[1],
                                      a2 + b3s[2], a3 + b3s[3]);
            *(float4*)(o + 4) = make_float4(a4 + b3s[4], a5 + b3s[5],
                                            a6 + b3s[6], a7 + b3s[7]);
            out[(size_t)B * 8 + mg] = -trs;
        }
        __syncthreads();
        buf ^= 1;
    }
#undef PHASE_A
}

extern "C" void kernel_launch(void* const* d_in, const int* in_sizes, int n_in,
                              void* d_out, int out_size) {
    const float* z  = (const float*)d_in[0];
    // d_in[1] = logp_z (unused by reference output)
    const float* t  = (const float*)d_in[2];
    const float* W1 = (const float*)d_in[3];
    const float* b1 = (const float*)d_in[4];
    const float* W2 = (const float*)d_in[5];
    const float* b2 = (const float*)d_in[6];
    const float* W3 = (const float*)d_in[7];
    const float* b3 = (const float*)d_in[8];
    float* out = (float*)d_out;
    int B = in_sizes[0] / Dd;

    cudaFuncSetAttribute(cnf_mma, cudaFuncAttributeMaxDynamicSharedMemorySize,
                         SM_TOTAL);

    prep<<<64, 256>>>(W1, W2, W3);
    cnf_mma<<<NBLK, THREADS, SM_TOTAL>>>(z, t, W1, b1, b2, W3, b3, out, B);
}

// round 14
// speedup vs baseline: 1.8294x; 1.7073x over previous
#include <cuda_runtime.h>
#include <cuda_fp16.h>
#include <cstdint>

// CNF_plain via HMMA fp16:
//   bacc = h @ W2,  racc = s1 @ E,  E = W2 .* (W1[:8,:]^T W3^T)
//   dz   = tanh(bacc+b2) @ W3  (also HMMA: acc-frag == A-frag layout)
// A: h single fp16 plane, s1 derived in regs; B: W2^T/E^T split hi+lo.
// R14: phase-A i remap (i0 = c8*16 + iq*4) -> W1/b1 LDS.128 now at 16B
// stride across iq groups: conflict-free (1 wf vs 4). Math identical.

#define Hh 128
#define Dd 8
#define THREADS 512
#define NBLK 148
#define TILE_M 128

#define ASTR 68   // u32 per A row (136 fp16 = 272B)
#define BSTR 68
#define HFU32 8704          // u32 per Hf buffer (128*68)

// SMEM byte offsets
#define SM_HF   0           // 2 x 34816
#define SM_WH   69632
#define SM_WL   104448
#define SM_EH   139264
#define SM_EL   174080
#define SM_W1   208896
#define SM_W3   213504
#define SM_B1   217600
#define SM_B2   218112
#define SM_B3   218624
#define SM_PTR  218688      // trace partials 8*128*4
#define SM_TOTAL 222784

static __device__ unsigned short g_wh[16384];  // [j][i] = f16_hi(W2[i,j])
static __device__ unsigned short g_wl[16384];
static __device__ unsigned short g_eh[16384];  // [j][i] = f16_hi(E[i,j])
static __device__ unsigned short g_el[16384];

__global__ void prep(const float* __restrict__ W1, const float* __restrict__ W2,
                     const float* __restrict__ W3) {
    int idx = blockIdx.x * blockDim.x + threadIdx.x;
    if (idx >= 16384) return;
    int j = idx >> 7, i = idx & 127;
    float c = 0.f;
#pragma unroll
    for (int d = 0; d < Dd; d++) c = fmaf(W1[d * Hh + i], W3[j * Dd + d], c);
    float w2 = W2[i * Hh + j];
    float e  = w2 * c;
    __half h;
    h = __float2half_rn(w2);
    g_wh[idx] = __half_as_ushort(h);
    g_wl[idx] = __half_as_ushort(__float2half_rn(w2 - __half2float(h)));
    h = __float2half_rn(e);
    g_eh[idx] = __half_as_ushort(h);
    g_el[idx] = __half_as_ushort(__float2half_rn(e - __half2float(h)));
}

__device__ __forceinline__ float tanha(float x) {
    float y; asm("tanh.approx.f32 %0,%1;" : "=f"(y) : "f"(x)); return y;
}

__device__ __forceinline__ uint32_t pkh2(float a, float b) {
    __half2 h = __floats2half2_rn(a, b);
    return *reinterpret_cast<uint32_t*>(&h);
}

__device__ __forceinline__ uint32_t s_from_h(uint32_t h) {
    __half2 hh = *reinterpret_cast<__half2*>(&h);
    __half2 s = __hfma2(__hneg2(hh), hh, __float2half2_rn(1.0f));
    return *reinterpret_cast<uint32_t*>(&s);
}

__device__ __forceinline__ void mmaf16(float* c, const uint32_t* a,
                                       const uint32_t* b) {
    asm volatile(
        "mma.sync.aligned.m16n8k16.row.col.f32.f16.f16.f32 "
        "{%0,%1,%2,%3}, {%4,%5,%6,%7}, {%8,%9}, {%0,%1,%2,%3};"
        : "+f"(c[0]), "+f"(c[1]), "+f"(c[2]), "+f"(c[3])
        : "r"(a[0]), "r"(a[1]), "r"(a[2]), "r"(a[3]), "r"(b[0]), "r"(b[1]));
}

__device__ __forceinline__ void ldsm4(uint32_t* r, uint32_t a) {
    asm volatile("ldmatrix.sync.aligned.m8n8.x4.shared.b16 {%0,%1,%2,%3},[%4];"
                 : "=r"(r[0]), "=r"(r[1]), "=r"(r[2]), "=r"(r[3]) : "r"(a));
}

__device__ __forceinline__ uint32_t s2u(const void* p) {
    uint32_t a;
    asm("{.reg .u64 t; cvta.to.shared.u64 t, %1; cvt.u32.u64 %0, t;}"
        : "=r"(a) : "l"(p));
    return a;
}

__global__ __launch_bounds__(THREADS, 1)
void cnf_mma(const float* __restrict__ z, const float* __restrict__ tptr,
             const float* __restrict__ W1, const float* __restrict__ b1,
             const float* __restrict__ b2,
             const float* __restrict__ W3, const float* __restrict__ b3,
             float* __restrict__ out, int B) {
    extern __shared__ char smem[];
    uint32_t* Hf = (uint32_t*)(smem + SM_HF);
    float* W1s = (float*)(smem + SM_W1);
    float* W3s = (float*)(smem + SM_W3);
    float* b1s = (float*)(smem + SM_B1);
    float* b2s = (float*)(smem + SM_B2);
    float* b3s = (float*)(smem + SM_B3);
    float* ptr_ = (float*)(smem + SM_PTR);    // [8 wn][128] trace partials

    const int tid = threadIdx.x;
    const int wid = tid >> 5, lane = tid & 31;
    const int wm = wid >> 3;          // m-half (64 rows)
    const int wn = wid & 7;           // n-eighth (16 cols)
    const int lq = lane & 3, lr = lane >> 2;

    // ---- stage B planes ----
    {
        const uint4* s0 = (const uint4*)g_wh;
        const uint4* s1 = (const uint4*)g_wl;
        const uint4* s2 = (const uint4*)g_eh;
        const uint4* s3 = (const uint4*)g_el;
        uint4* d0 = (uint4*)(smem + SM_WH);
        uint4* d1 = (uint4*)(smem + SM_WL);
        uint4* d2 = (uint4*)(smem + SM_EH);
        uint4* d3 = (uint4*)(smem + SM_EL);
        for (int k = tid; k < 2048; k += THREADS) {
            int j = k >> 4, c = k & 15;
            int dsti = j * 17 + c;
            d0[dsti] = s0[k]; d1[dsti] = s1[k];
            d2[dsti] = s2[k]; d3[dsti] = s3[k];
        }
    }
    for (int k = tid; k < 9 * Hh; k += THREADS) W1s[k] = W1[k];
    for (int k = tid; k < Hh * Dd; k += THREADS) W3s[k] = W3[k];
    if (tid < Hh) { b1s[tid] = b1[tid]; b2s[tid] = b2[tid]; }
    if (tid < Dd) b3s[tid] = b3[tid];
    __syncthreads();

    const float t = tptr[0];
    const int m = tid >> 2;           // phase-A sample (0..127)
    const int iq = tid & 3;           // phase-A i sub-offset (x4)

    // ---- ldmatrix per-thread addresses (buffer 0 base) ----
    const int grp = lane >> 3, l7 = lane & 7;
    uint32_t sAh[4];
#pragma unroll
    for (int mt = 0; mt < 4; mt++) {
        uint32_t off = (uint32_t)(((wm * 64 + mt * 16 + l7 + (grp & 1) * 8) * ASTR
                                   + (grp >> 1) * 4) * 4);
        sAh[mt] = s2u(smem + SM_HF) + off;
    }
    uint32_t sWh, sWl, sEh, sEl;
    {
        uint32_t off = (uint32_t)(((wn * 16 + l7 + (grp >> 1) * 8) * BSTR
                                   + (grp & 1) * 4) * 4);
        sWh = s2u(smem + SM_WH) + off;
        sWl = s2u(smem + SM_WL) + off;
        sEh = s2u(smem + SM_EH) + off;
        sEl = s2u(smem + SM_EL) + off;
    }

    // W3 b-frag (warp-constant)
    const float bA = b2s[wn * 16 + lq * 2];
    const float bB = b2s[wn * 16 + lq * 2 + 1];
    const float bC = b2s[wn * 16 + 8 + lq * 2];
    const float bD = b2s[wn * 16 + 9 + lq * 2];
    uint32_t w3b[2];
    {
        int j0 = wn * 16 + lq * 2;
        w3b[0] = pkh2(W3s[j0 * 8 + lr], W3s[(j0 + 1) * 8 + lr]);
        w3b[1] = pkh2(W3s[(j0 + 8) * 8 + lr], W3s[(j0 + 9) * 8 + lr]);
    }

    const int nTiles = B / TILE_M;

    // phase A: thread owns i = c8*16 + iq*4 .. +3 -> iq gives 16B stride
    // across the warp (conflict-free LDS.128), c8 walks 16-blocks.
#define PHASE_A(TILEV, BSEL) do {                                             \
        const int mg = (TILEV) * TILE_M + m;                                  \
        float4 z0 = *(const float4*)(z + (size_t)mg * 8);                     \
        float4 z1 = *(const float4*)(z + (size_t)mg * 8 + 4);                 \
        float zv[8] = {z0.x, z0.y, z0.z, z0.w, z1.x, z1.y, z1.z, z1.w};       \
        uint32_t* HfW = Hf + (BSEL) * HFU32;                                  \
        _Pragma("unroll")                                                     \
        for (int c8 = 0; c8 < 8; c8++) {                                      \
            int i0 = c8 * 16 + iq * 4;                                        \
            float4 acc = *(const float4*)(b1s + i0);                          \
            float4 wt = *(const float4*)(W1s + 8 * Hh + i0);                  \
            acc.x = fmaf(t, wt.x, acc.x); acc.y = fmaf(t, wt.y, acc.y);       \
            acc.z = fmaf(t, wt.z, acc.z); acc.w = fmaf(t, wt.w, acc.w);       \
            _Pragma("unroll")                                                 \
            for (int d = 0; d < 8; d++) {                                     \
                float4 w = *(const float4*)(W1s + d * Hh + i0);               \
                acc.x = fmaf(zv[d], w.x, acc.x);                              \
                acc.y = fmaf(zv[d], w.y, acc.y);                              \
                acc.z = fmaf(zv[d], w.z, acc.z);                              \
                acc.w = fmaf(zv[d], w.w, acc.w);                              \
            }                                                                 \
            int o = m * ASTR + c8 * 8 + iq * 2;                               \
            *(uint2*)&HfW[o] = make_uint2(pkh2(tanha(acc.x), tanha(acc.y)),   \
                                          pkh2(tanha(acc.z), tanha(acc.w))); \
        }                                                                     \
    } while (0)

    int tile = blockIdx.x;
    if (tile < nTiles) PHASE_A(tile, 0);
    __syncthreads();

    int buf = 0;
    for (; tile < nTiles; tile += gridDim.x) {
        const uint32_t bofs = (uint32_t)(buf * 34816);

        // ================= MMA phase (reads Hf[buf]) =================
        float cb[4][2][4], cr[4][2][4];
#pragma unroll
        for (int mt = 0; mt < 4; mt++)
#pragma unroll
            for (int nt = 0; nt < 2; nt++)
#pragma unroll
                for (int q = 0; q < 4; q++) { cb[mt][nt][q] = 0.f; cr[mt][nt][q] = 0.f; }

#pragma unroll 1
        for (int kt = 0; kt < 8; kt++) {
            const uint32_t ka = (uint32_t)(kt * 32);
            uint32_t bw[4], bl[4], be[4], bel[4];
            ldsm4(bw, sWh + ka);
            ldsm4(bl, sWl + ka);
            ldsm4(be, sEh + ka);
            ldsm4(bel, sEl + ka);
#pragma unroll
            for (int mt = 0; mt < 4; mt++) {
                uint32_t ah[4], as_[4];
                ldsm4(ah, sAh[mt] + bofs + ka);
#pragma unroll
                for (int r = 0; r < 4; r++) as_[r] = s_from_h(ah[r]);
                mmaf16(cb[mt][0], ah, bw);
                mmaf16(cb[mt][1], ah, bw + 2);
                mmaf16(cr[mt][0], as_, be);
                mmaf16(cr[mt][1], as_, be + 2);
                mmaf16(cb[mt][0], ah, bl);
                mmaf16(cb[mt][1], ah, bl + 2);
                mmaf16(cr[mt][0], as_, bel);
                mmaf16(cr[mt][1], as_, bel + 2);
            }
        }
        __syncthreads();   // all MMA reads of Hf[buf] complete

        // ========== epilogue: dz via HMMA, trace scalar ==========
        float* pdz = (float*)(smem + SM_HF + buf * 34816);  // [8 wn][128][8]
#pragma unroll
        for (int mt = 0; mt < 4; mt++) {
            float h00 = tanha(cb[mt][0][0] + bA), h01 = tanha(cb[mt][0][1] + bB);
            float h10 = tanha(cb[mt][1][0] + bC), h11 = tanha(cb[mt][1][1] + bD);
            float g00 = tanha(cb[mt][0][2] + bA), g01 = tanha(cb[mt][0][3] + bB);
            float g10 = tanha(cb[mt][1][2] + bC), g11 = tanha(cb[mt][1][3] + bD);
            uint32_t a[4] = {pkh2(h00, h01), pkh2(g00, g01),
                             pkh2(h10, h11), pkh2(g10, g11)};
            float dc[4] = {0.f, 0.f, 0.f, 0.f};
            mmaf16(dc, a, w3b);
            float trl = fmaf(fmaf(-h00, h00, 1.f), cr[mt][0][0], 0.f);
            trl = fmaf(fmaf(-h01, h01, 1.f), cr[mt][0][1], trl);
            trl = fmaf(fmaf(-h10, h10, 1.f), cr[mt][1][0], trl);
            trl = fmaf(fmaf(-h11, h11, 1.f), cr[mt][1][1], trl);
            float trh = fmaf(fmaf(-g00, g00, 1.f), cr[mt][0][2], 0.f);
            trh = fmaf(fmaf(-g01, g01, 1.f), cr[mt][0][3], trh);
            trh = fmaf(fmaf(-g10, g10, 1.f), cr[mt][1][2], trh);
            trh = fmaf(fmaf(-g11, g11, 1.f), cr[mt][1][3], trh);
            trl += __shfl_xor_sync(0xffffffffu, trl, 1);
            trl += __shfl_xor_sync(0xffffffffu, trl, 2);
            trh += __shfl_xor_sync(0xffffffffu, trh, 1);
            trh += __shfl_xor_sync(0xffffffffu, trh, 2);
            int row0 = wm * 64 + mt * 16 + lr;
            *(float2*)&pdz[(wn * 128 + row0) * 8 + lq * 2] =
                make_float2(dc[0], dc[1]);
            *(float2*)&pdz[(wn * 128 + row0 + 8) * 8 + lq * 2] =
                make_float2(dc[2], dc[3]);
            if (lq == 0) {
                ptr_[wn * 128 + row0] = trl;
                ptr_[wn * 128 + row0 + 8] = trh;
            }
        }

        // ========== phase A for next tile -> other buffer ==========
        {
            int tnext = tile + gridDim.x;
            if (tnext < nTiles) PHASE_A(tnext, buf ^ 1);
        }
        __syncthreads();

        // ========== combine 8 n-eighths per sample ==========
        if (tid < TILE_M) {
            float a0 = 0.f, a1 = 0.f, a2 = 0.f, a3 = 0.f;
            float a4 = 0.f, a5 = 0.f, a6 = 0.f, a7 = 0.f, trs = 0.f;
#pragma unroll
            for (int s = 0; s < 8; s++) {
                const float* pp = pdz + (s * 128 + tid) * 8;
                float4 x = *(const float4*)pp;
                float4 y = *(const float4*)(pp + 4);
                a0 += x.x; a1 += x.y; a2 += x.z; a3 += x.w;
                a4 += y.x; a5 += y.y; a6 += y.z; a7 += y.w;
                trs += ptr_[s * 128 + tid];
            }
            int mg = tile * TILE_M + tid;
            float* o = out + (size_t)mg * 8;
            *(float4*)o = make_float4(a0 + b3s[0], a1 + b3s[1],
                                      a2 + b3s[2], a3 + b3s[3]);
            *(float4*)(o + 4) = make_float4(a4 + b3s[4], a5 + b3s[5],
                                            a6 + b3s[6], a7 + b3s[7]);
            out[(size_t)B * 8 + mg] = -trs;
        }
        __syncthreads();
        buf ^= 1;
    }
#undef PHASE_A
}

extern "C" void kernel_launch(void* const* d_in, const int* in_sizes, int n_in,
                              void* d_out, int out_size) {
    const float* z  = (const float*)d_in[0];
    // d_in[1] = logp_z (unused by reference output)
    const float* t  = (const float*)d_in[2];
    const float* W1 = (const float*)d_in[3];
    const float* b1 = (const float*)d_in[4];
    const float* W2 = (const float*)d_in[5];
    const float* b2 = (const float*)d_in[6];
    const float* W3 = (const float*)d_in[7];
    const float* b3 = (const float*)d_in[8];
    float* out = (float*)d_out;
    int B = in_sizes[0] / Dd;

    cudaFuncSetAttribute(cnf_mma, cudaFuncAttributeMaxDynamicSharedMemorySize,
                         SM_TOTAL);

    prep<<<64, 256>>>(W1, W2, W3);
    cnf_mma<<<NBLK, THREADS, SM_TOTAL>>>(z, t, W1, b1, b2, W3, b3, out, B);
}

// round 15
// speedup vs baseline: 2.0538x; 1.1226x over previous
#include <cuda_runtime.h>
#include <cuda_fp16.h>
#include <cstdint>

// CNF_plain via HMMA fp16:
//   bacc = h @ W2 (hi+lo),  racc = s1 @ E (hi only),
//   E = W2 .* (W1[:8,:]^T W3^T),  dz = tanh(bacc+b2) @ W3 (HMMA epilogue)
// R15: drop E-lo pass (trace-only error +2^-12, dz untouched) -> 6 MMA/mt/kt
// instead of 8, 7 ldsm/kt instead of 8; combine distributed over 512 thr.

#define Hh 128
#define Dd 8
#define THREADS 512
#define NBLK 148
#define TILE_M 128

#define ASTR 68   // u32 per A row (136 fp16 = 272B)
#define BSTR 68
#define HFU32 8704          // u32 per Hf buffer (128*68)

// SMEM byte offsets
#define SM_HF   0           // 2 x 34816
#define SM_WH   69632
#define SM_WL   104448
#define SM_EH   139264
#define SM_W1   174080
#define SM_W3   178688
#define SM_B1   182784
#define SM_B2   183296
#define SM_B3   183808
#define SM_PTR  183872      // trace partials 8*128*4
#define SM_TOTAL 187968

static __device__ unsigned short g_wh[16384];  // [j][i] = f16_hi(W2[i,j])
static __device__ unsigned short g_wl[16384];
static __device__ unsigned short g_eh[16384];  // [j][i] = f16(E[i,j])

__global__ void prep(const float* __restrict__ W1, const float* __restrict__ W2,
                     const float* __restrict__ W3) {
    int idx = blockIdx.x * blockDim.x + threadIdx.x;
    if (idx >= 16384) return;
    int j = idx >> 7, i = idx & 127;
    float c = 0.f;
#pragma unroll
    for (int d = 0; d < Dd; d++) c = fmaf(W1[d * Hh + i], W3[j * Dd + d], c);
    float w2 = W2[i * Hh + j];
    float e  = w2 * c;
    __half h;
    h = __float2half_rn(w2);
    g_wh[idx] = __half_as_ushort(h);
    g_wl[idx] = __half_as_ushort(__float2half_rn(w2 - __half2float(h)));
    g_eh[idx] = __half_as_ushort(__float2half_rn(e));
}

__device__ __forceinline__ float tanha(float x) {
    float y; asm("tanh.approx.f32 %0,%1;" : "=f"(y) : "f"(x)); return y;
}

__device__ __forceinline__ uint32_t pkh2(float a, float b) {
    __half2 h = __floats2half2_rn(a, b);
    return *reinterpret_cast<uint32_t*>(&h);
}

__device__ __forceinline__ uint32_t s_from_h(uint32_t h) {
    __half2 hh = *reinterpret_cast<__half2*>(&h);
    __half2 s = __hfma2(__hneg2(hh), hh, __float2half2_rn(1.0f));
    return *reinterpret_cast<uint32_t*>(&s);
}

__device__ __forceinline__ void mmaf16(float* c, const uint32_t* a,
                                       const uint32_t* b) {
    asm volatile(
        "mma.sync.aligned.m16n8k16.row.col.f32.f16.f16.f32 "
        "{%0,%1,%2,%3}, {%4,%5,%6,%7}, {%8,%9}, {%0,%1,%2,%3};"
        : "+f"(c[0]), "+f"(c[1]), "+f"(c[2]), "+f"(c[3])
        : "r"(a[0]), "r"(a[1]), "r"(a[2]), "r"(a[3]), "r"(b[0]), "r"(b[1]));
}

__device__ __forceinline__ void ldsm4(uint32_t* r, uint32_t a) {
    asm volatile("ldmatrix.sync.aligned.m8n8.x4.shared.b16 {%0,%1,%2,%3},[%4];"
                 : "=r"(r[0]), "=r"(r[1]), "=r"(r[2]), "=r"(r[3]) : "r"(a));
}

__device__ __forceinline__ uint32_t s2u(const void* p) {
    uint32_t a;
    asm("{.reg .u64 t; cvta.to.shared.u64 t, %1; cvt.u32.u64 %0, t;}"
        : "=r"(a) : "l"(p));
    return a;
}

__global__ __launch_bounds__(THREADS, 1)
void cnf_mma(const float* __restrict__ z, const float* __restrict__ tptr,
             const float* __restrict__ W1, const float* __restrict__ b1,
             const float* __restrict__ b2,
             const float* __restrict__ W3, const float* __restrict__ b3,
             float* __restrict__ out, int B) {
    extern __shared__ char smem[];
    uint32_t* Hf = (uint32_t*)(smem + SM_HF);
    float* W1s = (float*)(smem + SM_W1);
    float* W3s = (float*)(smem + SM_W3);
    float* b1s = (float*)(smem + SM_B1);
    float* b2s = (float*)(smem + SM_B2);
    float* b3s = (float*)(smem + SM_B3);
    float* ptr_ = (float*)(smem + SM_PTR);    // [8 wn][128] trace partials

    const int tid = threadIdx.x;
    const int wid = tid >> 5, lane = tid & 31;
    const int wm = wid >> 3;          // m-half (64 rows)
    const int wn = wid & 7;           // n-eighth (16 cols)
    const int lq = lane & 3, lr = lane >> 2;

    // ---- stage B planes ----
    {
        const uint4* s0 = (const uint4*)g_wh;
        const uint4* s1 = (const uint4*)g_wl;
        const uint4* s2 = (const uint4*)g_eh;
        uint4* d0 = (uint4*)(smem + SM_WH);
        uint4* d1 = (uint4*)(smem + SM_WL);
        uint4* d2 = (uint4*)(smem + SM_EH);
        for (int k = tid; k < 2048; k += THREADS) {
            int j = k >> 4, c = k & 15;
            int dsti = j * 17 + c;
            d0[dsti] = s0[k]; d1[dsti] = s1[k]; d2[dsti] = s2[k];
        }
    }
    for (int k = tid; k < 9 * Hh; k += THREADS) W1s[k] = W1[k];
    for (int k = tid; k < Hh * Dd; k += THREADS) W3s[k] = W3[k];
    if (tid < Hh) { b1s[tid] = b1[tid]; b2s[tid] = b2[tid]; }
    if (tid < Dd) b3s[tid] = b3[tid];
    __syncthreads();

    const float t = tptr[0];
    const int m = tid >> 2;           // phase-A sample (0..127)
    const int iq = tid & 3;           // phase-A i sub-offset (x4)

    // ---- ldmatrix per-thread addresses (buffer 0 base) ----
    const int grp = lane >> 3, l7 = lane & 7;
    uint32_t sAh[4];
#pragma unroll
    for (int mt = 0; mt < 4; mt++) {
        uint32_t off = (uint32_t)(((wm * 64 + mt * 16 + l7 + (grp & 1) * 8) * ASTR
                                   + (grp >> 1) * 4) * 4);
        sAh[mt] = s2u(smem + SM_HF) + off;
    }
    uint32_t sWh, sWl, sEh;
    {
        uint32_t off = (uint32_t)(((wn * 16 + l7 + (grp >> 1) * 8) * BSTR
                                   + (grp & 1) * 4) * 4);
        sWh = s2u(smem + SM_WH) + off;
        sWl = s2u(smem + SM_WL) + off;
        sEh = s2u(smem + SM_EH) + off;
    }

    // W3 b-frag (warp-constant)
    const float bA = b2s[wn * 16 + lq * 2];
    const float bB = b2s[wn * 16 + lq * 2 + 1];
    const float bC = b2s[wn * 16 + 8 + lq * 2];
    const float bD = b2s[wn * 16 + 9 + lq * 2];
    uint32_t w3b[2];
    {
        int j0 = wn * 16 + lq * 2;
        w3b[0] = pkh2(W3s[j0 * 8 + lr], W3s[(j0 + 1) * 8 + lr]);
        w3b[1] = pkh2(W3s[(j0 + 8) * 8 + lr], W3s[(j0 + 9) * 8 + lr]);
    }

    const int nTiles = B / TILE_M;

    // phase A: thread owns i = c8*16 + iq*4 .. +3 (conflict-free LDS.128)
#define PHASE_A(TILEV, BSEL) do {                                             \
        const int mg = (TILEV) * TILE_M + m;                                  \
        float4 z0 = *(const float4*)(z + (size_t)mg * 8);                     \
        float4 z1 = *(const float4*)(z + (size_t)mg * 8 + 4);                 \
        float zv[8] = {z0.x, z0.y, z0.z, z0.w, z1.x, z1.y, z1.z, z1.w};       \
        uint32_t* HfW = Hf + (BSEL) * HFU32;                                  \
        _Pragma("unroll")                                                     \
        for (int c8 = 0; c8 < 8; c8++) {                                      \
            int i0 = c8 * 16 + iq * 4;                                        \
            float4 acc = *(const float4*)(b1s + i0);                          \
            float4 wt = *(const float4*)(W1s + 8 * Hh + i0);                  \
            acc.x = fmaf(t, wt.x, acc.x); acc.y = fmaf(t, wt.y, acc.y);       \
            acc.z = fmaf(t, wt.z, acc.z); acc.w = fmaf(t, wt.w, acc.w);       \
            _Pragma("unroll")                                                 \
            for (int d = 0; d < 8; d++) {                                     \
                float4 w = *(const float4*)(W1s + d * Hh + i0);               \
                acc.x = fmaf(zv[d], w.x, acc.x);                              \
                acc.y = fmaf(zv[d], w.y, acc.y);                              \
                acc.z = fmaf(zv[d], w.z, acc.z);                              \
                acc.w = fmaf(zv[d], w.w, acc.w);                              \
            }                                                                 \
            int o = m * ASTR + c8 * 8 + iq * 2;                               \
            *(uint2*)&HfW[o] = make_uint2(pkh2(tanha(acc.x), tanha(acc.y)),   \
                                          pkh2(tanha(acc.z), tanha(acc.w))); \
        }                                                                     \
    } while (0)

    int tile = blockIdx.x;
    if (tile < nTiles) PHASE_A(tile, 0);
    __syncthreads();

    int buf = 0;
    for (; tile < nTiles; tile += gridDim.x) {
        const uint32_t bofs = (uint32_t)(buf * 34816);

        // ================= MMA phase (reads Hf[buf]) =================
        float cb[4][2][4], cr[4][2][4];
#pragma unroll
        for (int mt = 0; mt < 4; mt++)
#pragma unroll
            for (int nt = 0; nt < 2; nt++)
#pragma unroll
                for (int q = 0; q < 4; q++) { cb[mt][nt][q] = 0.f; cr[mt][nt][q] = 0.f; }

#pragma unroll 1
        for (int kt = 0; kt < 8; kt++) {
            const uint32_t ka = (uint32_t)(kt * 32);
            uint32_t bw[4], bl[4], be[4];
            ldsm4(bw, sWh + ka);
            ldsm4(bl, sWl + ka);
            ldsm4(be, sEh + ka);
#pragma unroll
            for (int mt = 0; mt < 4; mt++) {
                uint32_t ah[4], as_[4];
                ldsm4(ah, sAh[mt] + bofs + ka);
#pragma unroll
                for (int r = 0; r < 4; r++) as_[r] = s_from_h(ah[r]);
                mmaf16(cb[mt][0], ah, bw);
                mmaf16(cb[mt][1], ah, bw + 2);
                mmaf16(cr[mt][0], as_, be);
                mmaf16(cr[mt][1], as_, be + 2);
                mmaf16(cb[mt][0], ah, bl);
                mmaf16(cb[mt][1], ah, bl + 2);
            }
        }
        __syncthreads();   // all MMA reads of Hf[buf] complete

        // ========== epilogue: dz via HMMA, trace scalar ==========
        float* pdz = (float*)(smem + SM_HF + buf * 34816);  // [8 wn][128][8]
#pragma unroll
        for (int mt = 0; mt < 4; mt++) {
            float h00 = tanha(cb[mt][0][0] + bA), h01 = tanha(cb[mt][0][1] + bB);
            float h10 = tanha(cb[mt][1][0] + bC), h11 = tanha(cb[mt][1][1] + bD);
            float g00 = tanha(cb[mt][0][2] + bA), g01 = tanha(cb[mt][0][3] + bB);
            float g10 = tanha(cb[mt][1][2] + bC), g11 = tanha(cb[mt][1][3] + bD);
            uint32_t a[4] = {pkh2(h00, h01), pkh2(g00, g01),
                             pkh2(h10, h11), pkh2(g10, g11)};
            float dc[4] = {0.f, 0.f, 0.f, 0.f};
            mmaf16(dc, a, w3b);
            float trl = fmaf(fmaf(-h00, h00, 1.f), cr[mt][0][0], 0.f);
            trl = fmaf(fmaf(-h01, h01, 1.f), cr[mt][0][1], trl);
            trl = fmaf(fmaf(-h10, h10, 1.f), cr[mt][1][0], trl);
            trl = fmaf(fmaf(-h11, h11, 1.f), cr[mt][1][1], trl);
            float trh = fmaf(fmaf(-g00, g00, 1.f), cr[mt][0][2], 0.f);
            trh = fmaf(fmaf(-g01, g01, 1.f), cr[mt][0][3], trh);
            trh = fmaf(fmaf(-g10, g10, 1.f), cr[mt][1][2], trh);
            trh = fmaf(fmaf(-g11, g11, 1.f), cr[mt][1][3], trh);
            trl += __shfl_xor_sync(0xffffffffu, trl, 1);
            trl += __shfl_xor_sync(0xffffffffu, trl, 2);
            trh += __shfl_xor_sync(0xffffffffu, trh, 1);
            trh += __shfl_xor_sync(0xffffffffu, trh, 2);
            int row0 = wm * 64 + mt * 16 + lr;
            *(float2*)&pdz[(wn * 128 + row0) * 8 + lq * 2] =
                make_float2(dc[0], dc[1]);
            *(float2*)&pdz[(wn * 128 + row0 + 8) * 8 + lq * 2] =
                make_float2(dc[2], dc[3]);
            if (lq == 0) {
                ptr_[wn * 128 + row0] = trl;
                ptr_[wn * 128 + row0 + 8] = trh;
            }
        }

        // ========== phase A for next tile -> other buffer ==========
        {
            int tnext = tile + gridDim.x;
            if (tnext < nTiles) PHASE_A(tnext, buf ^ 1);
        }
        __syncthreads();

        // ========== combine (all 512 threads): s=tid&127, g=tid>>7 ==========
        {
            int s = tid & 127, g = tid >> 7;
            float a0 = 0.f, a1 = 0.f, trs = 0.f;
#pragma unroll
            for (int seg = 0; seg < 8; seg++) {
                float2 x = *(const float2*)&pdz[(seg * 128 + s) * 8 + g * 2];
                a0 += x.x; a1 += x.y;
                if (g == 0) trs += ptr_[seg * 128 + s];
            }
            int mg = tile * TILE_M + s;
            *(float2*)(out + (size_t)mg * 8 + g * 2) =
                make_float2(a0 + b3s[g * 2], a1 + b3s[g * 2 + 1]);
            if (g == 0) out[(size_t)B * 8 + mg] = -trs;
        }
        __syncthreads();
        buf ^= 1;
    }
#undef PHASE_A
}

extern "C" void kernel_launch(void* const* d_in, const int* in_sizes, int n_in,
                              void* d_out, int out_size) {
    const float* z  = (const float*)d_in[0];
    // d_in[1] = logp_z (unused by reference output)
    const float* t  = (const float*)d_in[2];
    const float* W1 = (const float*)d_in[3];
    const float* b1 = (const float*)d_in[4];
    const float* W2 = (const float*)d_in[5];
    const float* b2 = (const float*)d_in[6];
    const float* W3 = (const float*)d_in[7];
    const float* b3 = (const float*)d_in[8];
    float* out = (float*)d_out;
    int B = in_sizes[0] / Dd;

    cudaFuncSetAttribute(cnf_mma, cudaFuncAttributeMaxDynamicSharedMemorySize,
                         SM_TOTAL);

    prep<<<64, 256>>>(W1, W2, W3);
    cnf_mma<<<NBLK, THREADS, SM_TOTAL>>>(z, t, W1, b1, b2, W3, b3, out, B);
}

// round 17
// speedup vs baseline: 2.0548x; 1.0005x over previous
#include <cuda_runtime.h>
#include <cuda_fp16.h>
#include <cstdint>

// CNF_plain via HMMA fp16:
//   bacc = h @ W2 (hi+lo),  racc = s1 @ E (hi only),
//   E = W2 .* (W1[:8,:]^T W3^T),  dz = tanh(bacc+b2) @ W3 (HMMA epilogue)
// R16: tanh.approx.f16x2 (MUFU halved; epilogue tanh output IS the dz
// A-frag), pdz un-aliased -> 2 barriers/tile instead of 3.

#define Hh 128
#define Dd 8
#define THREADS 512
#define NBLK 148
#define TILE_M 128

#define ASTR 68   // u32 per A row (136 fp16 = 272B)
#define BSTR 68
#define HFU32 8704          // u32 per Hf buffer (128*68)

// SMEM byte offsets
#define SM_HF   0           // 2 x 34816
#define SM_WH   69632
#define SM_WL   104448
#define SM_EH   139264
#define SM_W1   174080
#define SM_W3   178688
#define SM_B1   182784
#define SM_B2   183296
#define SM_B3   183808
#define SM_PTR  183872      // trace partials 8*128*4
#define SM_PDZ  187968      // dz partials 8*128*8*4
#define SM_TOTAL 220736

static __device__ unsigned short g_wh[16384];  // [j][i] = f16_hi(W2[i,j])
static __device__ unsigned short g_wl[16384];
static __device__ unsigned short g_eh[16384];  // [j][i] = f16(E[i,j])

__global__ void prep(const float* __restrict__ W1, const float* __restrict__ W2,
                     const float* __restrict__ W3) {
    int idx = blockIdx.x * blockDim.x + threadIdx.x;
    if (idx >= 16384) return;
    int j = idx >> 7, i = idx & 127;
    float c = 0.f;
#pragma unroll
    for (int d = 0; d < Dd; d++) c = fmaf(W1[d * Hh + i], W3[j * Dd + d], c);
    float w2 = W2[i * Hh + j];
    float e  = w2 * c;
    __half h;
    h = __float2half_rn(w2);
    g_wh[idx] = __half_as_ushort(h);
    g_wl[idx] = __half_as_ushort(__float2half_rn(w2 - __half2float(h)));
    g_eh[idx] = __half_as_ushort(__float2half_rn(e));
}

__device__ __forceinline__ uint32_t pkh2(float a, float b) {
    __half2 h = __floats2half2_rn(a, b);
    return *reinterpret_cast<uint32_t*>(&h);
}

// packed fp16x2 tanh (MUFU, 1 op per pair)
__device__ __forceinline__ uint32_t tanh2(uint32_t x) {
    uint32_t y;
    asm("tanh.approx.f16x2 %0,%1;" : "=r"(y) : "r"(x));
    return y;
}

__device__ __forceinline__ uint32_t s_from_h(uint32_t h) {
    __half2 hh = *reinterpret_cast<__half2*>(&h);
    __half2 s = __hfma2(__hneg2(hh), hh, __float2half2_rn(1.0f));
    return *reinterpret_cast<uint32_t*>(&s);
}

__device__ __forceinline__ float2 h2f2(uint32_t h) {
    return __half22float2(*reinterpret_cast<__half2*>(&h));
}

__device__ __forceinline__ void mmaf16(float* c, const uint32_t* a,
                                       const uint32_t* b) {
    asm volatile(
        "mma.sync.aligned.m16n8k16.row.col.f32.f16.f16.f32 "
        "{%0,%1,%2,%3}, {%4,%5,%6,%7}, {%8,%9}, {%0,%1,%2,%3};"
        : "+f"(c[0]), "+f"(c[1]), "+f"(c[2]), "+f"(c[3])
        : "r"(a[0]), "r"(a[1]), "r"(a[2]), "r"(a[3]), "r"(b[0]), "r"(b[1]));
}

__device__ __forceinline__ void ldsm4(uint32_t* r, uint32_t a) {
    asm volatile("ldmatrix.sync.aligned.m8n8.x4.shared.b16 {%0,%1,%2,%3},[%4];"
                 : "=r"(r[0]), "=r"(r[1]), "=r"(r[2]), "=r"(r[3]) : "r"(a));
}

__device__ __forceinline__ uint32_t s2u(const void* p) {
    uint32_t a;
    asm("{.reg .u64 t; cvta.to.shared.u64 t, %1; cvt.u32.u64 %0, t;}"
        : "=r"(a) : "l"(p));
    return a;
}

__global__ __launch_bounds__(THREADS, 1)
void cnf_mma(const float* __restrict__ z, const float* __restrict__ tptr,
             const float* __restrict__ W1, const float* __restrict__ b1,
             const float* __restrict__ b2,
             const float* __restrict__ W3, const float* __restrict__ b3,
             float* __restrict__ out, int B) {
    extern __shared__ char smem[];
    uint32_t* Hf = (uint32_t*)(smem + SM_HF);
    float* W1s = (float*)(smem + SM_W1);
    float* W3s = (float*)(smem + SM_W3);
    float* b1s = (float*)(smem + SM_B1);
    float* b2s = (float*)(smem + SM_B2);
    float* b3s = (float*)(smem + SM_B3);
    float* ptr_ = (float*)(smem + SM_PTR);    // [8 wn][128] trace partials
    float* pdz  = (float*)(smem + SM_PDZ);    // [8 wn][128][8] dz partials

    const int tid = threadIdx.x;
    const int wid = tid >> 5, lane = tid & 31;
    const int wm = wid >> 3;          // m-half (64 rows)
    const int wn = wid & 7;           // n-eighth (16 cols)
    const int lq = lane & 3, lr = lane >> 2;

    // ---- stage B planes ----
    {
        const uint4* s0 = (const uint4*)g_wh;
        const uint4* s1 = (const uint4*)g_wl;
        const uint4* s2 = (const uint4*)g_eh;
        uint4* d0 = (uint4*)(smem + SM_WH);
        uint4* d1 = (uint4*)(smem + SM_WL);
        uint4* d2 = (uint4*)(smem + SM_EH);
        for (int k = tid; k < 2048; k += THREADS) {
            int j = k >> 4, c = k & 15;
            int dsti = j * 17 + c;
            d0[dsti] = s0[k]; d1[dsti] = s1[k]; d2[dsti] = s2[k];
        }
    }
    for (int k = tid; k < 9 * Hh; k += THREADS) W1s[k] = W1[k];
    for (int k = tid; k < Hh * Dd; k += THREADS) W3s[k] = W3[k];
    if (tid < Hh) { b1s[tid] = b1[tid]; b2s[tid] = b2[tid]; }
    if (tid < Dd) b3s[tid] = b3[tid];
    __syncthreads();

    const float t = tptr[0];
    const int m = tid >> 2;           // phase-A sample (0..127)
    const int iq = tid & 3;           // phase-A i sub-offset (x4)

    // ---- ldmatrix per-thread addresses (buffer 0 base) ----
    const int grp = lane >> 3, l7 = lane & 7;
    uint32_t sAh[4];
#pragma unroll
    for (int mt = 0; mt < 4; mt++) {
        uint32_t off = (uint32_t)(((wm * 64 + mt * 16 + l7 + (grp & 1) * 8) * ASTR
                                   + (grp >> 1) * 4) * 4);
        sAh[mt] = s2u(smem + SM_HF) + off;
    }
    uint32_t sWh, sWl, sEh;
    {
        uint32_t off = (uint32_t)(((wn * 16 + l7 + (grp >> 1) * 8) * BSTR
                                   + (grp & 1) * 4) * 4);
        sWh = s2u(smem + SM_WH) + off;
        sWl = s2u(smem + SM_WL) + off;
        sEh = s2u(smem + SM_EH) + off;
    }

    // W3 b-frag + b2 frag (warp-constant)
    const float bA = b2s[wn * 16 + lq * 2];
    const float bB = b2s[wn * 16 + lq * 2 + 1];
    const float bC = b2s[wn * 16 + 8 + lq * 2];
    const float bD = b2s[wn * 16 + 9 + lq * 2];
    uint32_t w3b[2];
    {
        int j0 = wn * 16 + lq * 2;
        w3b[0] = pkh2(W3s[j0 * 8 + lr], W3s[(j0 + 1) * 8 + lr]);
        w3b[1] = pkh2(W3s[(j0 + 8) * 8 + lr], W3s[(j0 + 9) * 8 + lr]);
    }

    const int nTiles = B / TILE_M;

    // phase A: thread owns i = c8*16 + iq*4 .. +3 (conflict-free LDS.128).
    // tanh on packed fp16 pairs (1 MUFU per pair).
#define PHASE_A(TILEV, BSEL) do {                                             \
        const int mg = (TILEV) * TILE_M + m;                                  \
        float4 z0 = *(const float4*)(z + (size_t)mg * 8);                     \
        float4 z1 = *(const float4*)(z + (size_t)mg * 8 + 4);                 \
        float zv[8] = {z0.x, z0.y, z0.z, z0.w, z1.x, z1.y, z1.z, z1.w};       \
        uint32_t* HfW = Hf + (BSEL) * HFU32;                                  \
        _Pragma("unroll")                                                     \
        for (int c8 = 0; c8 < 8; c8++) {                                      \
            int i0 = c8 * 16 + iq * 4;                                        \
            float4 acc = *(const float4*)(b1s + i0);                          \
            float4 wt = *(const float4*)(W1s + 8 * Hh + i0);                  \
            acc.x = fmaf(t, wt.x, acc.x); acc.y = fmaf(t, wt.y, acc.y);       \
            acc.z = fmaf(t, wt.z, acc.z); acc.w = fmaf(t, wt.w, acc.w);       \
            _Pragma("unroll")                                                 \
            for (int d = 0; d < 8; d++) {                                     \
                float4 w = *(const float4*)(W1s + d * Hh + i0);               \
                acc.x = fmaf(zv[d], w.x, acc.x);                              \
                acc.y = fmaf(zv[d], w.y, acc.y);                              \
                acc.z = fmaf(zv[d], w.z, acc.z);                              \
                acc.w = fmaf(zv[d], w.w, acc.w);                              \
            }                                                                 \
            int o = m * ASTR + c8 * 8 + iq * 2;                               \
            *(uint2*)&HfW[o] = make_uint2(tanh2(pkh2(acc.x, acc.y)),          \
                                          tanh2(pkh2(acc.z, acc.w)));        \
        }                                                                     \
    } while (0)

    int tile = blockIdx.x;
    if (tile < nTiles) PHASE_A(tile, 0);
    __syncthreads();

    int buf = 0;
    for (; tile < nTiles; tile += gridDim.x) {
        const uint32_t bofs = (uint32_t)(buf * 34816);

        // ================= MMA phase (reads Hf[buf]) =================
        float cb[4][2][4], cr[4][2][4];
#pragma unroll
        for (int mt = 0; mt < 4; mt++)
#pragma unroll
            for (int nt = 0; nt < 2; nt++)
#pragma unroll
                for (int q = 0; q < 4; q++) { cb[mt][nt][q] = 0.f; cr[mt][nt][q] = 0.f; }

#pragma unroll 1
        for (int kt = 0; kt < 8; kt++) {
            const uint32_t ka = (uint32_t)(kt * 32);
            uint32_t bw[4], bl[4], be[4];
            ldsm4(bw, sWh + ka);
            ldsm4(bl, sWl + ka);
            ldsm4(be, sEh + ka);
#pragma unroll
            for (int mt = 0; mt < 4; mt++) {
                uint32_t ah[4], as_[4];
                ldsm4(ah, sAh[mt] + bofs + ka);
#pragma unroll
                for (int r = 0; r < 4; r++) as_[r] = s_from_h(ah[r]);
                mmaf16(cb[mt][0], ah, bw);
                mmaf16(cb[mt][1], ah, bw + 2);
                mmaf16(cr[mt][0], as_, be);
                mmaf16(cr[mt][1], as_, be + 2);
                mmaf16(cb[mt][0], ah, bl);
                mmaf16(cb[mt][1], ah, bl + 2);
            }
        }
        __syncthreads();   // prior combine done in all warps; Hf[buf] free

        // ========== epilogue: dz via HMMA, trace from packed h ==========
#pragma unroll
        for (int mt = 0; mt < 4; mt++) {
            // packed h fragments: tanh2 output IS the dz A-fragment
            uint32_t a0 = tanh2(pkh2(cb[mt][0][0] + bA, cb[mt][0][1] + bB));
            uint32_t a1 = tanh2(pkh2(cb[mt][0][2] + bA, cb[mt][0][3] + bB));
            uint32_t a2 = tanh2(pkh2(cb[mt][1][0] + bC, cb[mt][1][1] + bD));
            uint32_t a3 = tanh2(pkh2(cb[mt][1][2] + bC, cb[mt][1][3] + bD));
            uint32_t a[4] = {a0, a1, a2, a3};
            float dc[4] = {0.f, 0.f, 0.f, 0.f};
            mmaf16(dc, a, w3b);
            // trace: s2 = 1-h^2 from packed h
            float2 s0 = h2f2(s_from_h(a0));
            float2 s1 = h2f2(s_from_h(a1));
            float2 s2 = h2f2(s_from_h(a2));
            float2 s3 = h2f2(s_from_h(a3));
            float trl = s0.x * cr[mt][0][0];
            trl = fmaf(s0.y, cr[mt][0][1], trl);
            trl = fmaf(s2.x, cr[mt][1][0], trl);
            trl = fmaf(s2.y, cr[mt][1][1], trl);
            float trh = s1.x * cr[mt][0][2];
            trh = fmaf(s1.y, cr[mt][0][3], trh);
            trh = fmaf(s3.x, cr[mt][1][2], trh);
            trh = fmaf(s3.y, cr[mt][1][3], trh);
            trl += __shfl_xor_sync(0xffffffffu, trl, 1);
            trl += __shfl_xor_sync(0xffffffffu, trl, 2);
            trh += __shfl_xor_sync(0xffffffffu, trh, 1);
            trh += __shfl_xor_sync(0xffffffffu, trh, 2);
            int row0 = wm * 64 + mt * 16 + lr;
            *(float2*)&pdz[(wn * 128 + row0) * 8 + lq * 2] =
                make_float2(dc[0], dc[1]);
            *(float2*)&pdz[(wn * 128 + row0 + 8) * 8 + lq * 2] =
                make_float2(dc[2], dc[3]);
            if (lq == 0) {
                ptr_[wn * 128 + row0] = trl;
                ptr_[wn * 128 + row0 + 8] = trh;
            }
        }

        // ========== phase A for next tile -> other buffer ==========
        {
            int tnext = tile + gridDim.x;
            if (tnext < nTiles) PHASE_A(tnext, buf ^ 1);
        }
        __syncthreads();

        // ========== combine (all 512 threads): s=tid&127, g=tid>>7 ==========
        {
            int s = tid & 127, g = tid >> 7;
            float a0 = 0.f, a1 = 0.f, trs = 0.f;
#pragma unroll
            for (int seg = 0; seg < 8; seg++) {
                float2 x = *(const float2*)&pdz[(seg * 128 + s) * 8 + g * 2];
                a0 += x.x; a1 += x.y;
                if (g == 0) trs += ptr_[seg * 128 + s];
            }
            int mg = tile * TILE_M + s;
            *(float2*)(out + (size_t)mg * 8 + g * 2) =
                make_float2(a0 + b3s[g * 2], a1 + b3s[g * 2 + 1]);
            if (g == 0) out[(size_t)B * 8 + mg] = -trs;
        }
        // no barrier: per-warp order (combine -> MMA -> sync) protects pdz
        buf ^= 1;
    }
#undef PHASE_A
}

extern "C" void kernel_launch(void* const* d_in, const int* in_sizes, int n_in,
                              void* d_out, int out_size) {
    const float* z  = (const float*)d_in[0];
    // d_in[1] = logp_z (unused by reference output)
    const float* t  = (const float*)d_in[2];
    const float* W1 = (const float*)d_in[3];
    const float* b1 = (const float*)d_in[4];
    const float* W2 = (const float*)d_in[5];
    const float* b2 = (const float*)d_in[6];
    const float* W3 = (const float*)d_in[7];
    const float* b3 = (const float*)d_in[8];
    float* out = (float*)d_out;
    int B = in_sizes[0] / Dd;

    cudaFuncSetAttribute(cnf_mma, cudaFuncAttributeMaxDynamicSharedMemorySize,
                         SM_TOTAL);

    prep<<<64, 256>>>(W1, W2, W3);
    cnf_mma<<<NBLK, THREADS, SM_TOTAL>>>(z, t, W1, b1, b2, W3, b3, out, B);
}